// round 12
// baseline (speedup 1.0000x reference)
#include <cuda_runtime.h>

#define TPB 128
#define EPSV 1e-5f

__device__ __forceinline__ float fast_tanh(float x) {
    float r;
    asm("tanh.approx.f32 %0, %1;" : "=f"(r) : "f"(x));
    return r;
}
__device__ __forceinline__ float fast_silu(float z) {
    return z * (0.5f * fast_tanh(0.5f * z) + 0.5f);
}

// Block-resident GridNet step: dual-batch interleaved, 3 CTAs/SM (R6 loop).
// Single pass per CTA (grid 4096) for finer wave granularity: halves the
// tail quantum of the 4.6-wave launch. Weights re-read 8x but W fits in L2.
__global__ __launch_bounds__(TPB, 3)
void gridnet_kernel(const float* __restrict__ W,
                    const float* __restrict__ Bias,
                    const float* __restrict__ Rscale,
                    const float* __restrict__ X,
                    float* __restrict__ Y)
{
    __shared__ float sa0[2000], sa1[2000];   // batch A double buffer
    __shared__ float sb0[2000], sb1[2000];   // batch B double buffer
    __shared__ float red[2][16];             // [parity][batch*8 + warp*2 + {S,S2}]

    const int t    = threadIdx.x;
    const int k2   = t & 3;
    const int j2   = (t >> 2) & 3;
    const int ii   = t >> 4;           // 0..7
    const int lane = t & 31;
    const int wid  = t >> 5;

    const int sb = blockIdx.x >> 3;    // spatial block 0..511
    const int bp = blockIdx.x & 7;     // batch pair 0..7
    const int bk = sb & 7, bn = (sb >> 3) & 7, bm = sb >> 6;

    const int gi  = bm * 8 + ii;
    const int gj0 = bn * 8 + 2 * j2;
    const int gk0 = bk * 8 + 2 * k2;
    const int jb  = 2 * j2, kb = 2 * k2;

    // ---- weights, sum-of-weights, bias, residual scale into registers ----
    float w[27][2][2];
    float sumw[2][2] = {{0.f, 0.f}, {0.f, 0.f}};
#pragma unroll
    for (int tap = 0; tap < 27; ++tap) {
#pragma unroll
        for (int jj = 0; jj < 2; ++jj) {
            const float2 wv = *reinterpret_cast<const float2*>(
                W + (((size_t)tap * 64 + gi) * 64 + (gj0 + jj)) * 64 + gk0);
            w[tap][jj][0] = wv.x; w[tap][jj][1] = wv.y;
            sumw[jj][0] += wv.x;  sumw[jj][1] += wv.y;
        }
    }
    float bbv[2][2], rsv[2][2];
#pragma unroll
    for (int jj = 0; jj < 2; ++jj) {
        const float2 bv = *reinterpret_cast<const float2*>(
            Bias + ((size_t)gi * 64 + gj0 + jj) * 64 + gk0);
        const float2 rv = *reinterpret_cast<const float2*>(
            Rscale + ((size_t)gi * 64 + gj0 + jj) * 64 + gk0);
        bbv[jj][0] = bv.x; bbv[jj][1] = bv.y;
        rsv[jj][0] = rv.x; rsv[jj][1] = rv.y;
    }

    const int curoff = (ii + 1) * 200 + (jb + 1) * 20 + (kb + 1);

    const int ba  = bp * 2;                 // batch A
    const int bbi = ba + 1;                 // batch B
    const float* Xa = X + (size_t)ba  * 262144;
    const float* Xb = X + (size_t)bbi * 262144;

    // ---- load both padded blocks, fold initial sums ----
    float Sa = 0.f, S2a = 0.f, Sb = 0.f, S2b = 0.f;
    for (int n = t; n < 1000; n += TPB) {
        const int a = n / 100;
        const int r = n - a * 100;
        const int q = r / 10;
        const int c = r - q * 10;
        const int gm = bm * 8 + a - 1;
        const int gn = bn * 8 + q - 1;
        const int gq = bk * 8 + c - 1;
        float va = 0.f, vb = 0.f;
        if ((unsigned)gm < 64u && (unsigned)gn < 64u && (unsigned)gq < 64u) {
            const size_t gidx = ((size_t)gm * 64 + gn) * 64 + gq;
            va = Xa[gidx];
            vb = Xb[gidx];
        }
        const int off = a * 200 + q * 20 + c;
        sa0[off] = va; sa1[off] = va;
        sb0[off] = vb; sb1[off] = vb;
        Sa += va; S2a += va * va;
        Sb += vb; S2b += vb * vb;
    }
#pragma unroll
    for (int o = 16; o; o >>= 1) {
        Sa  += __shfl_xor_sync(0xffffffffu, Sa,  o);
        S2a += __shfl_xor_sync(0xffffffffu, S2a, o);
        Sb  += __shfl_xor_sync(0xffffffffu, Sb,  o);
        S2b += __shfl_xor_sync(0xffffffffu, S2b, o);
    }
    if (lane == 0) {
        red[1][wid * 2]     = Sa; red[1][wid * 2 + 1]     = S2a;
        red[1][8 + wid * 2] = Sb; red[1][8 + wid * 2 + 1] = S2b;
    }
    __syncthreads();

    // current inner values for this thread's 4 outputs, each batch
    float ca[2][2], cb[2][2];
#pragma unroll
    for (int jj = 0; jj < 2; ++jj)
#pragma unroll
        for (int kk = 0; kk < 2; ++kk) {
            ca[jj][kk] = sa0[curoff + jj * 20 + kk];
            cb[jj][kk] = sb0[curoff + jj * 20 + kk];
        }

    Sa = 0.f; S2a = 0.f; Sb = 0.f; S2b = 0.f;   // running totals

#pragma unroll 2
    for (int it = 0; it < 8; ++it) {
        const float* rda = (it & 1) ? sa1 : sa0;
        float*       wra = (it & 1) ? sa0 : sa1;
        const float* rdb = (it & 1) ? sb1 : sb0;
        float*       wrb = (it & 1) ? sb0 : sb1;
        const int    pb  = (it + 1) & 1;

        // cross-warp partial loads issued early (hidden by FMA block)
        const float dSaS  = (red[pb][0] + red[pb][2]) + (red[pb][4] + red[pb][6]);
        const float dS2aS = (red[pb][1] + red[pb][3]) + (red[pb][5] + red[pb][7]);
        const float dSbS  = (red[pb][8]  + red[pb][10]) + (red[pb][12] + red[pb][14]);
        const float dS2bS = (red[pb][9]  + red[pb][11]) + (red[pb][13] + red[pb][15]);

        float aa[2][2] = {{0.f, 0.f}, {0.f, 0.f}};
        float ab[2][2] = {{0.f, 0.f}, {0.f, 0.f}};
#pragma unroll
        for (int dx = 0; dx < 3; ++dx) {
            const int poff = (ii + dx) * 200 + jb * 20 + kb;
#pragma unroll
            for (int r = 0; r < 4; ++r) {
                float va[4], vb[4];
                {
                    const float2 a0 = *reinterpret_cast<const float2*>(rda + poff + r * 20);
                    const float2 a1 = *reinterpret_cast<const float2*>(rda + poff + r * 20 + 2);
                    va[0] = a0.x; va[1] = a0.y; va[2] = a1.x; va[3] = a1.y;
                    const float2 b0 = *reinterpret_cast<const float2*>(rdb + poff + r * 20);
                    const float2 b1 = *reinterpret_cast<const float2*>(rdb + poff + r * 20 + 2);
                    vb[0] = b0.x; vb[1] = b0.y; vb[2] = b1.x; vb[3] = b1.y;
                }
                // row r feeds (dy,jj) with dy + jj == r
#pragma unroll
                for (int dy = 0; dy < 3; ++dy) {
#pragma unroll
                    for (int jj = 0; jj < 2; ++jj) {
                        if (dy + jj == r) {
#pragma unroll
                            for (int dz = 0; dz < 3; ++dz) {
                                const int tap = dx * 9 + dy * 3 + dz;
                                aa[jj][0] = fmaf(va[dz],     w[tap][jj][0], aa[jj][0]);
                                aa[jj][1] = fmaf(va[dz + 1], w[tap][jj][1], aa[jj][1]);
                                ab[jj][0] = fmaf(vb[dz],     w[tap][jj][0], ab[jj][0]);
                                ab[jj][1] = fmaf(vb[dz + 1], w[tap][jj][1], ab[jj][1]);
                            }
                        }
                    }
                }
            }
        }

        // fold deferred partials; per-batch stats
        Sa += dSaS; S2a += dS2aS;
        Sb += dSbS; S2b += dS2bS;
        const float ma  = Sa * (1.0f / 1000.0f);
        const float ra  = rsqrtf(S2a * (1.0f / 1000.0f) - ma * ma + EPSV);
        const float mb  = Sb * (1.0f / 1000.0f);
        const float rb2 = rsqrtf(S2b * (1.0f / 1000.0f) - mb * mb + EPSV);

        // epilogue both batches; store new values before the reduction
        float dSa = 0.f, dS2a = 0.f, dSb = 0.f, dS2b = 0.f;
#pragma unroll
        for (int jj = 0; jj < 2; ++jj)
#pragma unroll
            for (int kk = 0; kk < 2; ++kk) {
                const float za = fmaf(-ma, sumw[jj][kk], aa[jj][kk]) * ra + bbv[jj][kk];
                const float na = fmaf(rsv[jj][kk], fast_silu(za), ca[jj][kk]);
                wra[curoff + jj * 20 + kk] = na;
                dSa  += na - ca[jj][kk];
                dS2a += fmaf(na, na, -ca[jj][kk] * ca[jj][kk]);
                ca[jj][kk] = na;

                const float zb = fmaf(-mb, sumw[jj][kk], ab[jj][kk]) * rb2 + bbv[jj][kk];
                const float nb = fmaf(rsv[jj][kk], fast_silu(zb), cb[jj][kk]);
                wrb[curoff + jj * 20 + kk] = nb;
                dSb  += nb - cb[jj][kk];
                dS2b += fmaf(nb, nb, -cb[jj][kk] * cb[jj][kk]);
                cb[jj][kk] = nb;
            }

        // four independent butterfly chains — pipeline through shfl
#pragma unroll
        for (int o = 16; o; o >>= 1) {
            dSa  += __shfl_xor_sync(0xffffffffu, dSa,  o);
            dS2a += __shfl_xor_sync(0xffffffffu, dS2a, o);
            dSb  += __shfl_xor_sync(0xffffffffu, dSb,  o);
            dS2b += __shfl_xor_sync(0xffffffffu, dS2b, o);
        }
        const int rbp = it & 1;
        if (lane == 0) {
            red[rbp][wid * 2]     = dSa; red[rbp][wid * 2 + 1]     = dS2a;
            red[rbp][8 + wid * 2] = dSb; red[rbp][8 + wid * 2 + 1] = dS2b;
        }
        __syncthreads();
    }

    // ---- write final outputs for both batches ----
    float* Ya = Y + (size_t)ba  * 262144;
    float* Yb = Y + (size_t)bbi * 262144;
#pragma unroll
    for (int jj = 0; jj < 2; ++jj) {
        const size_t o = ((size_t)gi * 64 + gj0 + jj) * 64 + gk0;
        float2 oa; oa.x = ca[jj][0]; oa.y = ca[jj][1];
        float2 ob; ob.x = cb[jj][0]; ob.y = cb[jj][1];
        *reinterpret_cast<float2*>(Ya + o) = oa;
        *reinterpret_cast<float2*>(Yb + o) = ob;
    }
}

extern "C" void kernel_launch(void* const* d_in, const int* in_sizes, int n_in,
                              void* d_out, int out_size)
{
    const float* W  = (const float*)d_in[0];   // (27,64,64,64)
    const float* Bb = (const float*)d_in[1];   // (64,64,64)
    const float* Rs = (const float*)d_in[2];   // (64,64,64)
    const float* X  = (const float*)d_in[3];   // (16,64,64,64)
    float* Y = (float*)d_out;

    gridnet_kernel<<<4096, TPB>>>(W, Bb, Rs, X, Y);
}

// round 13
// speedup vs baseline: 1.1000x; 1.1000x over previous
#include <cuda_runtime.h>

#define TPB 128
#define EPSV 1e-5f

__device__ __forceinline__ float fast_tanh(float x) {
    float r;
    asm("tanh.approx.f32 %0, %1;" : "=f"(r) : "f"(x));
    return r;
}
__device__ __forceinline__ float fast_silu(float z) {
    return z * (0.5f * fast_tanh(0.5f * z) + 0.5f);
}

// Block-resident GridNet step: dual-batch interleaved, 3 CTAs/SM (R6 champion)
// + one-time nanosleep stagger to desynchronize the 3 co-resident wave-1 CTAs
// so their FMA blocks fill each other's barrier/reduction bubbles.
__global__ __launch_bounds__(TPB, 3)
void gridnet_kernel(const float* __restrict__ W,
                    const float* __restrict__ Bias,
                    const float* __restrict__ Rscale,
                    const float* __restrict__ X,
                    float* __restrict__ Y)
{
    __shared__ float sa0[2000], sa1[2000];   // batch A double buffer
    __shared__ float sb0[2000], sb1[2000];   // batch B double buffer
    __shared__ float red[2][16];             // [parity][batch*8 + warp*2 + {S,S2}]

    // stagger co-resident wave-1 CTAs (bids b, b+148, b+296 share an SM)
    {
        const unsigned phase = (blockIdx.x / 148u) % 3u;
        if (phase) __nanosleep(phase * 300u);
    }

    const int t    = threadIdx.x;
    const int k2   = t & 3;
    const int j2   = (t >> 2) & 3;
    const int ii   = t >> 4;           // 0..7
    const int lane = t & 31;
    const int wid  = t >> 5;

    const int sb = blockIdx.x >> 2;    // spatial block 0..511
    const int bg = blockIdx.x & 3;     // batch group 0..3
    const int bk = sb & 7, bn = (sb >> 3) & 7, bm = sb >> 6;

    const int gi  = bm * 8 + ii;
    const int gj0 = bn * 8 + 2 * j2;
    const int gk0 = bk * 8 + 2 * k2;
    const int jb  = 2 * j2, kb = 2 * k2;

    // ---- weights, sum-of-weights, bias, residual scale into registers ----
    float w[27][2][2];
    float sumw[2][2] = {{0.f, 0.f}, {0.f, 0.f}};
#pragma unroll
    for (int tap = 0; tap < 27; ++tap) {
#pragma unroll
        for (int jj = 0; jj < 2; ++jj) {
            const float2 wv = *reinterpret_cast<const float2*>(
                W + (((size_t)tap * 64 + gi) * 64 + (gj0 + jj)) * 64 + gk0);
            w[tap][jj][0] = wv.x; w[tap][jj][1] = wv.y;
            sumw[jj][0] += wv.x;  sumw[jj][1] += wv.y;
        }
    }
    float bbv[2][2], rsv[2][2];
#pragma unroll
    for (int jj = 0; jj < 2; ++jj) {
        const float2 bv = *reinterpret_cast<const float2*>(
            Bias + ((size_t)gi * 64 + gj0 + jj) * 64 + gk0);
        const float2 rv = *reinterpret_cast<const float2*>(
            Rscale + ((size_t)gi * 64 + gj0 + jj) * 64 + gk0);
        bbv[jj][0] = bv.x; bbv[jj][1] = bv.y;
        rsv[jj][0] = rv.x; rsv[jj][1] = rv.y;
    }

    const int curoff = (ii + 1) * 200 + (jb + 1) * 20 + (kb + 1);

#pragma unroll 1
    for (int pass = 0; pass < 2; ++pass) {
        const int ba  = bg * 4 + pass * 2;      // batch A
        const int bbi = ba + 1;                 // batch B
        const float* Xa = X + (size_t)ba  * 262144;
        const float* Xb = X + (size_t)bbi * 262144;

        // ---- load both padded blocks, fold initial sums ----
        float Sa = 0.f, S2a = 0.f, Sb = 0.f, S2b = 0.f;
        for (int n = t; n < 1000; n += TPB) {
            const int a = n / 100;
            const int r = n - a * 100;
            const int q = r / 10;
            const int c = r - q * 10;
            const int gm = bm * 8 + a - 1;
            const int gn = bn * 8 + q - 1;
            const int gq = bk * 8 + c - 1;
            float va = 0.f, vb = 0.f;
            if ((unsigned)gm < 64u && (unsigned)gn < 64u && (unsigned)gq < 64u) {
                const size_t gidx = ((size_t)gm * 64 + gn) * 64 + gq;
                va = Xa[gidx];
                vb = Xb[gidx];
            }
            const int off = a * 200 + q * 20 + c;
            sa0[off] = va; sa1[off] = va;
            sb0[off] = vb; sb1[off] = vb;
            Sa += va; S2a += va * va;
            Sb += vb; S2b += vb * vb;
        }
#pragma unroll
        for (int o = 16; o; o >>= 1) {
            Sa  += __shfl_xor_sync(0xffffffffu, Sa,  o);
            S2a += __shfl_xor_sync(0xffffffffu, S2a, o);
            Sb  += __shfl_xor_sync(0xffffffffu, Sb,  o);
            S2b += __shfl_xor_sync(0xffffffffu, S2b, o);
        }
        if (lane == 0) {
            red[1][wid * 2]     = Sa; red[1][wid * 2 + 1]     = S2a;
            red[1][8 + wid * 2] = Sb; red[1][8 + wid * 2 + 1] = S2b;
        }
        __syncthreads();

        // current inner values for this thread's 4 outputs, each batch
        float ca[2][2], cb[2][2];
#pragma unroll
        for (int jj = 0; jj < 2; ++jj)
#pragma unroll
            for (int kk = 0; kk < 2; ++kk) {
                ca[jj][kk] = sa0[curoff + jj * 20 + kk];
                cb[jj][kk] = sb0[curoff + jj * 20 + kk];
            }

        Sa = 0.f; S2a = 0.f; Sb = 0.f; S2b = 0.f;   // running totals

#pragma unroll 2
        for (int it = 0; it < 8; ++it) {
            const float* rda = (it & 1) ? sa1 : sa0;
            float*       wra = (it & 1) ? sa0 : sa1;
            const float* rdb = (it & 1) ? sb1 : sb0;
            float*       wrb = (it & 1) ? sb0 : sb1;
            const int    pb  = (it + 1) & 1;

            // cross-warp partial loads issued early (hidden by FMA block)
            const float dSaS  = (red[pb][0] + red[pb][2]) + (red[pb][4] + red[pb][6]);
            const float dS2aS = (red[pb][1] + red[pb][3]) + (red[pb][5] + red[pb][7]);
            const float dSbS  = (red[pb][8]  + red[pb][10]) + (red[pb][12] + red[pb][14]);
            const float dS2bS = (red[pb][9]  + red[pb][11]) + (red[pb][13] + red[pb][15]);

            float aa[2][2] = {{0.f, 0.f}, {0.f, 0.f}};
            float ab[2][2] = {{0.f, 0.f}, {0.f, 0.f}};
#pragma unroll
            for (int dx = 0; dx < 3; ++dx) {
                const int poff = (ii + dx) * 200 + jb * 20 + kb;
#pragma unroll
                for (int r = 0; r < 4; ++r) {
                    float va[4], vb[4];
                    {
                        const float2 a0 = *reinterpret_cast<const float2*>(rda + poff + r * 20);
                        const float2 a1 = *reinterpret_cast<const float2*>(rda + poff + r * 20 + 2);
                        va[0] = a0.x; va[1] = a0.y; va[2] = a1.x; va[3] = a1.y;
                        const float2 b0 = *reinterpret_cast<const float2*>(rdb + poff + r * 20);
                        const float2 b1 = *reinterpret_cast<const float2*>(rdb + poff + r * 20 + 2);
                        vb[0] = b0.x; vb[1] = b0.y; vb[2] = b1.x; vb[3] = b1.y;
                    }
                    // row r feeds (dy,jj) with dy + jj == r
#pragma unroll
                    for (int dy = 0; dy < 3; ++dy) {
#pragma unroll
                        for (int jj = 0; jj < 2; ++jj) {
                            if (dy + jj == r) {
#pragma unroll
                                for (int dz = 0; dz < 3; ++dz) {
                                    const int tap = dx * 9 + dy * 3 + dz;
                                    aa[jj][0] = fmaf(va[dz],     w[tap][jj][0], aa[jj][0]);
                                    aa[jj][1] = fmaf(va[dz + 1], w[tap][jj][1], aa[jj][1]);
                                    ab[jj][0] = fmaf(vb[dz],     w[tap][jj][0], ab[jj][0]);
                                    ab[jj][1] = fmaf(vb[dz + 1], w[tap][jj][1], ab[jj][1]);
                                }
                            }
                        }
                    }
                }
            }

            // fold deferred partials; per-batch stats
            Sa += dSaS; S2a += dS2aS;
            Sb += dSbS; S2b += dS2bS;
            const float ma  = Sa * (1.0f / 1000.0f);
            const float ra  = rsqrtf(S2a * (1.0f / 1000.0f) - ma * ma + EPSV);
            const float mb  = Sb * (1.0f / 1000.0f);
            const float rb2 = rsqrtf(S2b * (1.0f / 1000.0f) - mb * mb + EPSV);

            // epilogue both batches; store new values before the reduction
            float dSa = 0.f, dS2a = 0.f, dSb = 0.f, dS2b = 0.f;
#pragma unroll
            for (int jj = 0; jj < 2; ++jj)
#pragma unroll
                for (int kk = 0; kk < 2; ++kk) {
                    const float za = fmaf(-ma, sumw[jj][kk], aa[jj][kk]) * ra + bbv[jj][kk];
                    const float na = fmaf(rsv[jj][kk], fast_silu(za), ca[jj][kk]);
                    wra[curoff + jj * 20 + kk] = na;
                    dSa  += na - ca[jj][kk];
                    dS2a += fmaf(na, na, -ca[jj][kk] * ca[jj][kk]);
                    ca[jj][kk] = na;

                    const float zb = fmaf(-mb, sumw[jj][kk], ab[jj][kk]) * rb2 + bbv[jj][kk];
                    const float nb = fmaf(rsv[jj][kk], fast_silu(zb), cb[jj][kk]);
                    wrb[curoff + jj * 20 + kk] = nb;
                    dSb  += nb - cb[jj][kk];
                    dS2b += fmaf(nb, nb, -cb[jj][kk] * cb[jj][kk]);
                    cb[jj][kk] = nb;
                }

            // four independent butterfly chains — pipeline through shfl
#pragma unroll
            for (int o = 16; o; o >>= 1) {
                dSa  += __shfl_xor_sync(0xffffffffu, dSa,  o);
                dS2a += __shfl_xor_sync(0xffffffffu, dS2a, o);
                dSb  += __shfl_xor_sync(0xffffffffu, dSb,  o);
                dS2b += __shfl_xor_sync(0xffffffffu, dS2b, o);
            }
            const int rbp = it & 1;
            if (lane == 0) {
                red[rbp][wid * 2]     = dSa; red[rbp][wid * 2 + 1]     = dS2a;
                red[rbp][8 + wid * 2] = dSb; red[rbp][8 + wid * 2 + 1] = dS2b;
            }
            __syncthreads();
        }

        // ---- write final outputs for both batches ----
        float* Ya = Y + (size_t)ba  * 262144;
        float* Yb = Y + (size_t)bbi * 262144;
#pragma unroll
        for (int jj = 0; jj < 2; ++jj) {
            const size_t o = ((size_t)gi * 64 + gj0 + jj) * 64 + gk0;
            float2 oa; oa.x = ca[jj][0]; oa.y = ca[jj][1];
            float2 ob; ob.x = cb[jj][0]; ob.y = cb[jj][1];
            *reinterpret_cast<float2*>(Ya + o) = oa;
            *reinterpret_cast<float2*>(Yb + o) = ob;
        }
        // it=7 barrier already ordered all SMEM reads before next pass's writes.
    }
}

extern "C" void kernel_launch(void* const* d_in, const int* in_sizes, int n_in,
                              void* d_out, int out_size)
{
    const float* W  = (const float*)d_in[0];   // (27,64,64,64)
    const float* Bb = (const float*)d_in[1];   // (64,64,64)
    const float* Rs = (const float*)d_in[2];   // (64,64,64)
    const float* X  = (const float*)d_in[3];   // (16,64,64,64)
    float* Y = (float*)d_out;

    gridnet_kernel<<<2048, TPB>>>(W, Bb, Rs, X, Y);
}

// round 14
// speedup vs baseline: 1.1066x; 1.0060x over previous
#include <cuda_runtime.h>

#define TPB 128
#define EPSV 1e-5f

__device__ __forceinline__ float fast_tanh(float x) {
    float r;
    asm("tanh.approx.f32 %0, %1;" : "=f"(r) : "f"(x));
    return r;
}
__device__ __forceinline__ float fast_silu(float z) {
    return z * (0.5f * fast_tanh(0.5f * z) + 0.5f);
}

// Block-resident GridNet step: dual-batch interleaved, 3 CTAs/SM (R6 champion),
// iteration loop unrolled 4x (compile-time buffer parity, wider sched window).
__global__ __launch_bounds__(TPB, 3)
void gridnet_kernel(const float* __restrict__ W,
                    const float* __restrict__ Bias,
                    const float* __restrict__ Rscale,
                    const float* __restrict__ X,
                    float* __restrict__ Y)
{
    __shared__ float sa0[2000], sa1[2000];   // batch A double buffer
    __shared__ float sb0[2000], sb1[2000];   // batch B double buffer
    __shared__ float red[2][16];             // [parity][batch*8 + warp*2 + {S,S2}]

    const int t    = threadIdx.x;
    const int k2   = t & 3;
    const int j2   = (t >> 2) & 3;
    const int ii   = t >> 4;           // 0..7
    const int lane = t & 31;
    const int wid  = t >> 5;

    const int sb = blockIdx.x >> 2;    // spatial block 0..511
    const int bg = blockIdx.x & 3;     // batch group 0..3
    const int bk = sb & 7, bn = (sb >> 3) & 7, bm = sb >> 6;

    const int gi  = bm * 8 + ii;
    const int gj0 = bn * 8 + 2 * j2;
    const int gk0 = bk * 8 + 2 * k2;
    const int jb  = 2 * j2, kb = 2 * k2;

    // ---- weights, sum-of-weights, bias, residual scale into registers ----
    float w[27][2][2];
    float sumw[2][2] = {{0.f, 0.f}, {0.f, 0.f}};
#pragma unroll
    for (int tap = 0; tap < 27; ++tap) {
#pragma unroll
        for (int jj = 0; jj < 2; ++jj) {
            const float2 wv = *reinterpret_cast<const float2*>(
                W + (((size_t)tap * 64 + gi) * 64 + (gj0 + jj)) * 64 + gk0);
            w[tap][jj][0] = wv.x; w[tap][jj][1] = wv.y;
            sumw[jj][0] += wv.x;  sumw[jj][1] += wv.y;
        }
    }
    float bbv[2][2], rsv[2][2];
#pragma unroll
    for (int jj = 0; jj < 2; ++jj) {
        const float2 bv = *reinterpret_cast<const float2*>(
            Bias + ((size_t)gi * 64 + gj0 + jj) * 64 + gk0);
        const float2 rv = *reinterpret_cast<const float2*>(
            Rscale + ((size_t)gi * 64 + gj0 + jj) * 64 + gk0);
        bbv[jj][0] = bv.x; bbv[jj][1] = bv.y;
        rsv[jj][0] = rv.x; rsv[jj][1] = rv.y;
    }

    const int curoff = (ii + 1) * 200 + (jb + 1) * 20 + (kb + 1);

#pragma unroll 1
    for (int pass = 0; pass < 2; ++pass) {
        const int ba  = bg * 4 + pass * 2;      // batch A
        const int bbi = ba + 1;                 // batch B
        const float* Xa = X + (size_t)ba  * 262144;
        const float* Xb = X + (size_t)bbi * 262144;

        // ---- load both padded blocks, fold initial sums ----
        float Sa = 0.f, S2a = 0.f, Sb = 0.f, S2b = 0.f;
        for (int n = t; n < 1000; n += TPB) {
            const int a = n / 100;
            const int r = n - a * 100;
            const int q = r / 10;
            const int c = r - q * 10;
            const int gm = bm * 8 + a - 1;
            const int gn = bn * 8 + q - 1;
            const int gq = bk * 8 + c - 1;
            float va = 0.f, vb = 0.f;
            if ((unsigned)gm < 64u && (unsigned)gn < 64u && (unsigned)gq < 64u) {
                const size_t gidx = ((size_t)gm * 64 + gn) * 64 + gq;
                va = Xa[gidx];
                vb = Xb[gidx];
            }
            const int off = a * 200 + q * 20 + c;
            sa0[off] = va; sa1[off] = va;
            sb0[off] = vb; sb1[off] = vb;
            Sa += va; S2a += va * va;
            Sb += vb; S2b += vb * vb;
        }
#pragma unroll
        for (int o = 16; o; o >>= 1) {
            Sa  += __shfl_xor_sync(0xffffffffu, Sa,  o);
            S2a += __shfl_xor_sync(0xffffffffu, S2a, o);
            Sb  += __shfl_xor_sync(0xffffffffu, Sb,  o);
            S2b += __shfl_xor_sync(0xffffffffu, S2b, o);
        }
        if (lane == 0) {
            red[1][wid * 2]     = Sa; red[1][wid * 2 + 1]     = S2a;
            red[1][8 + wid * 2] = Sb; red[1][8 + wid * 2 + 1] = S2b;
        }
        __syncthreads();

        // current inner values for this thread's 4 outputs, each batch
        float ca[2][2], cb[2][2];
#pragma unroll
        for (int jj = 0; jj < 2; ++jj)
#pragma unroll
            for (int kk = 0; kk < 2; ++kk) {
                ca[jj][kk] = sa0[curoff + jj * 20 + kk];
                cb[jj][kk] = sb0[curoff + jj * 20 + kk];
            }

        Sa = 0.f; S2a = 0.f; Sb = 0.f; S2b = 0.f;   // running totals

#pragma unroll 4
        for (int it = 0; it < 8; ++it) {
            const float* rda = (it & 1) ? sa1 : sa0;
            float*       wra = (it & 1) ? sa0 : sa1;
            const float* rdb = (it & 1) ? sb1 : sb0;
            float*       wrb = (it & 1) ? sb0 : sb1;
            const int    pb  = (it + 1) & 1;

            // cross-warp partial loads issued early (hidden by FMA block)
            const float dSaS  = (red[pb][0] + red[pb][2]) + (red[pb][4] + red[pb][6]);
            const float dS2aS = (red[pb][1] + red[pb][3]) + (red[pb][5] + red[pb][7]);
            const float dSbS  = (red[pb][8]  + red[pb][10]) + (red[pb][12] + red[pb][14]);
            const float dS2bS = (red[pb][9]  + red[pb][11]) + (red[pb][13] + red[pb][15]);

            float aa[2][2] = {{0.f, 0.f}, {0.f, 0.f}};
            float ab[2][2] = {{0.f, 0.f}, {0.f, 0.f}};
#pragma unroll
            for (int dx = 0; dx < 3; ++dx) {
                const int poff = (ii + dx) * 200 + jb * 20 + kb;
#pragma unroll
                for (int r = 0; r < 4; ++r) {
                    float va[4], vb[4];
                    {
                        const float2 a0 = *reinterpret_cast<const float2*>(rda + poff + r * 20);
                        const float2 a1 = *reinterpret_cast<const float2*>(rda + poff + r * 20 + 2);
                        va[0] = a0.x; va[1] = a0.y; va[2] = a1.x; va[3] = a1.y;
                        const float2 b0 = *reinterpret_cast<const float2*>(rdb + poff + r * 20);
                        const float2 b1 = *reinterpret_cast<const float2*>(rdb + poff + r * 20 + 2);
                        vb[0] = b0.x; vb[1] = b0.y; vb[2] = b1.x; vb[3] = b1.y;
                    }
                    // row r feeds (dy,jj) with dy + jj == r
#pragma unroll
                    for (int dy = 0; dy < 3; ++dy) {
#pragma unroll
                        for (int jj = 0; jj < 2; ++jj) {
                            if (dy + jj == r) {
#pragma unroll
                                for (int dz = 0; dz < 3; ++dz) {
                                    const int tap = dx * 9 + dy * 3 + dz;
                                    aa[jj][0] = fmaf(va[dz],     w[tap][jj][0], aa[jj][0]);
                                    aa[jj][1] = fmaf(va[dz + 1], w[tap][jj][1], aa[jj][1]);
                                    ab[jj][0] = fmaf(vb[dz],     w[tap][jj][0], ab[jj][0]);
                                    ab[jj][1] = fmaf(vb[dz + 1], w[tap][jj][1], ab[jj][1]);
                                }
                            }
                        }
                    }
                }
            }

            // fold deferred partials; per-batch stats
            Sa += dSaS; S2a += dS2aS;
            Sb += dSbS; S2b += dS2bS;
            const float ma  = Sa * (1.0f / 1000.0f);
            const float ra  = rsqrtf(S2a * (1.0f / 1000.0f) - ma * ma + EPSV);
            const float mb  = Sb * (1.0f / 1000.0f);
            const float rb2 = rsqrtf(S2b * (1.0f / 1000.0f) - mb * mb + EPSV);

            // epilogue both batches; store new values before the reduction
            float dSa = 0.f, dS2a = 0.f, dSb = 0.f, dS2b = 0.f;
#pragma unroll
            for (int jj = 0; jj < 2; ++jj)
#pragma unroll
                for (int kk = 0; kk < 2; ++kk) {
                    const float za = fmaf(-ma, sumw[jj][kk], aa[jj][kk]) * ra + bbv[jj][kk];
                    const float na = fmaf(rsv[jj][kk], fast_silu(za), ca[jj][kk]);
                    wra[curoff + jj * 20 + kk] = na;
                    dSa  += na - ca[jj][kk];
                    dS2a += fmaf(na, na, -ca[jj][kk] * ca[jj][kk]);
                    ca[jj][kk] = na;

                    const float zb = fmaf(-mb, sumw[jj][kk], ab[jj][kk]) * rb2 + bbv[jj][kk];
                    const float nb = fmaf(rsv[jj][kk], fast_silu(zb), cb[jj][kk]);
                    wrb[curoff + jj * 20 + kk] = nb;
                    dSb  += nb - cb[jj][kk];
                    dS2b += fmaf(nb, nb, -cb[jj][kk] * cb[jj][kk]);
                    cb[jj][kk] = nb;
                }

            // four independent butterfly chains — pipeline through shfl
#pragma unroll
            for (int o = 16; o; o >>= 1) {
                dSa  += __shfl_xor_sync(0xffffffffu, dSa,  o);
                dS2a += __shfl_xor_sync(0xffffffffu, dS2a, o);
                dSb  += __shfl_xor_sync(0xffffffffu, dSb,  o);
                dS2b += __shfl_xor_sync(0xffffffffu, dS2b, o);
            }
            const int rbp = it & 1;
            if (lane == 0) {
                red[rbp][wid * 2]     = dSa; red[rbp][wid * 2 + 1]     = dS2a;
                red[rbp][8 + wid * 2] = dSb; red[rbp][8 + wid * 2 + 1] = dS2b;
            }
            __syncthreads();
        }

        // ---- write final outputs for both batches ----
        float* Ya = Y + (size_t)ba  * 262144;
        float* Yb = Y + (size_t)bbi * 262144;
#pragma unroll
        for (int jj = 0; jj < 2; ++jj) {
            const size_t o = ((size_t)gi * 64 + gj0 + jj) * 64 + gk0;
            float2 oa; oa.x = ca[jj][0]; oa.y = ca[jj][1];
            float2 ob; ob.x = cb[jj][0]; ob.y = cb[jj][1];
            *reinterpret_cast<float2*>(Ya + o) = oa;
            *reinterpret_cast<float2*>(Yb + o) = ob;
        }
        // it=7 barrier already ordered all SMEM reads before next pass's writes.
    }
}

extern "C" void kernel_launch(void* const* d_in, const int* in_sizes, int n_in,
                              void* d_out, int out_size)
{
    const float* W  = (const float*)d_in[0];   // (27,64,64,64)
    const float* Bb = (const float*)d_in[1];   // (64,64,64)
    const float* Rs = (const float*)d_in[2];   // (64,64,64)
    const float* X  = (const float*)d_in[3];   // (16,64,64,64)
    float* Y = (float*)d_out;

    gridnet_kernel<<<2048, TPB>>>(W, Bb, Rs, X, Y);
}

// round 15
// speedup vs baseline: 1.1212x; 1.0132x over previous
#include <cuda_runtime.h>

#define TPB 128
#define EPSV 1e-5f

__device__ __forceinline__ float fast_tanh(float x) {
    float r;
    asm("tanh.approx.f32 %0, %1;" : "=f"(r) : "f"(x));
    return r;
}
__device__ __forceinline__ float fast_silu(float z) {
    return z * (0.5f * fast_tanh(0.5f * z) + 0.5f);
}

// Block-resident GridNet step: dual-batch interleaved AND 3 CTAs/SM.
// Rolling-row FMA structure keeps only one 4-value row live per batch
// (row r feeds the (dy,jj) pairs with dy+jj==r), cutting v-regs 32 -> 8
// so the dual-batch version fits the 170-reg budget of 3 CTAs/SM.
// Converged champion configuration (R6): 104.9us.
__global__ __launch_bounds__(TPB, 3)
void gridnet_kernel(const float* __restrict__ W,
                    const float* __restrict__ Bias,
                    const float* __restrict__ Rscale,
                    const float* __restrict__ X,
                    float* __restrict__ Y)
{
    __shared__ float sa0[2000], sa1[2000];   // batch A double buffer
    __shared__ float sb0[2000], sb1[2000];   // batch B double buffer
    __shared__ float red[2][16];             // [parity][batch*8 + warp*2 + {S,S2}]

    const int t    = threadIdx.x;
    const int k2   = t & 3;
    const int j2   = (t >> 2) & 3;
    const int ii   = t >> 4;           // 0..7
    const int lane = t & 31;
    const int wid  = t >> 5;

    const int sb = blockIdx.x >> 2;    // spatial block 0..511
    const int bg = blockIdx.x & 3;     // batch group 0..3
    const int bk = sb & 7, bn = (sb >> 3) & 7, bm = sb >> 6;

    const int gi  = bm * 8 + ii;
    const int gj0 = bn * 8 + 2 * j2;
    const int gk0 = bk * 8 + 2 * k2;
    const int jb  = 2 * j2, kb = 2 * k2;

    // ---- weights, sum-of-weights, bias, residual scale into registers ----
    float w[27][2][2];
    float sumw[2][2] = {{0.f, 0.f}, {0.f, 0.f}};
#pragma unroll
    for (int tap = 0; tap < 27; ++tap) {
#pragma unroll
        for (int jj = 0; jj < 2; ++jj) {
            const float2 wv = *reinterpret_cast<const float2*>(
                W + (((size_t)tap * 64 + gi) * 64 + (gj0 + jj)) * 64 + gk0);
            w[tap][jj][0] = wv.x; w[tap][jj][1] = wv.y;
            sumw[jj][0] += wv.x;  sumw[jj][1] += wv.y;
        }
    }
    float bbv[2][2], rsv[2][2];
#pragma unroll
    for (int jj = 0; jj < 2; ++jj) {
        const float2 bv = *reinterpret_cast<const float2*>(
            Bias + ((size_t)gi * 64 + gj0 + jj) * 64 + gk0);
        const float2 rv = *reinterpret_cast<const float2*>(
            Rscale + ((size_t)gi * 64 + gj0 + jj) * 64 + gk0);
        bbv[jj][0] = bv.x; bbv[jj][1] = bv.y;
        rsv[jj][0] = rv.x; rsv[jj][1] = rv.y;
    }

    const int curoff = (ii + 1) * 200 + (jb + 1) * 20 + (kb + 1);

#pragma unroll 1
    for (int pass = 0; pass < 2; ++pass) {
        const int ba  = bg * 4 + pass * 2;      // batch A
        const int bbi = ba + 1;                 // batch B
        const float* Xa = X + (size_t)ba  * 262144;
        const float* Xb = X + (size_t)bbi * 262144;

        // ---- load both padded blocks, fold initial sums ----
        float Sa = 0.f, S2a = 0.f, Sb = 0.f, S2b = 0.f;
        for (int n = t; n < 1000; n += TPB) {
            const int a = n / 100;
            const int r = n - a * 100;
            const int q = r / 10;
            const int c = r - q * 10;
            const int gm = bm * 8 + a - 1;
            const int gn = bn * 8 + q - 1;
            const int gq = bk * 8 + c - 1;
            float va = 0.f, vb = 0.f;
            if ((unsigned)gm < 64u && (unsigned)gn < 64u && (unsigned)gq < 64u) {
                const size_t gidx = ((size_t)gm * 64 + gn) * 64 + gq;
                va = Xa[gidx];
                vb = Xb[gidx];
            }
            const int off = a * 200 + q * 20 + c;
            sa0[off] = va; sa1[off] = va;
            sb0[off] = vb; sb1[off] = vb;
            Sa += va; S2a += va * va;
            Sb += vb; S2b += vb * vb;
        }
#pragma unroll
        for (int o = 16; o; o >>= 1) {
            Sa  += __shfl_xor_sync(0xffffffffu, Sa,  o);
            S2a += __shfl_xor_sync(0xffffffffu, S2a, o);
            Sb  += __shfl_xor_sync(0xffffffffu, Sb,  o);
            S2b += __shfl_xor_sync(0xffffffffu, S2b, o);
        }
        if (lane == 0) {
            red[1][wid * 2]     = Sa; red[1][wid * 2 + 1]     = S2a;
            red[1][8 + wid * 2] = Sb; red[1][8 + wid * 2 + 1] = S2b;
        }
        __syncthreads();

        // current inner values for this thread's 4 outputs, each batch
        float ca[2][2], cb[2][2];
#pragma unroll
        for (int jj = 0; jj < 2; ++jj)
#pragma unroll
            for (int kk = 0; kk < 2; ++kk) {
                ca[jj][kk] = sa0[curoff + jj * 20 + kk];
                cb[jj][kk] = sb0[curoff + jj * 20 + kk];
            }

        Sa = 0.f; S2a = 0.f; Sb = 0.f; S2b = 0.f;   // running totals

#pragma unroll 2
        for (int it = 0; it < 8; ++it) {
            const float* rda = (it & 1) ? sa1 : sa0;
            float*       wra = (it & 1) ? sa0 : sa1;
            const float* rdb = (it & 1) ? sb1 : sb0;
            float*       wrb = (it & 1) ? sb0 : sb1;
            const int    pb  = (it + 1) & 1;

            // cross-warp partial loads issued early (hidden by FMA block)
            const float dSaS  = (red[pb][0] + red[pb][2]) + (red[pb][4] + red[pb][6]);
            const float dS2aS = (red[pb][1] + red[pb][3]) + (red[pb][5] + red[pb][7]);
            const float dSbS  = (red[pb][8]  + red[pb][10]) + (red[pb][12] + red[pb][14]);
            const float dS2bS = (red[pb][9]  + red[pb][11]) + (red[pb][13] + red[pb][15]);

            float aa[2][2] = {{0.f, 0.f}, {0.f, 0.f}};
            float ab[2][2] = {{0.f, 0.f}, {0.f, 0.f}};
#pragma unroll
            for (int dx = 0; dx < 3; ++dx) {
                const int poff = (ii + dx) * 200 + jb * 20 + kb;
#pragma unroll
                for (int r = 0; r < 4; ++r) {
                    float va[4], vb[4];
                    {
                        const float2 a0 = *reinterpret_cast<const float2*>(rda + poff + r * 20);
                        const float2 a1 = *reinterpret_cast<const float2*>(rda + poff + r * 20 + 2);
                        va[0] = a0.x; va[1] = a0.y; va[2] = a1.x; va[3] = a1.y;
                        const float2 b0 = *reinterpret_cast<const float2*>(rdb + poff + r * 20);
                        const float2 b1 = *reinterpret_cast<const float2*>(rdb + poff + r * 20 + 2);
                        vb[0] = b0.x; vb[1] = b0.y; vb[2] = b1.x; vb[3] = b1.y;
                    }
                    // row r feeds (dy,jj) with dy + jj == r
#pragma unroll
                    for (int dy = 0; dy < 3; ++dy) {
#pragma unroll
                        for (int jj = 0; jj < 2; ++jj) {
                            if (dy + jj == r) {
#pragma unroll
                                for (int dz = 0; dz < 3; ++dz) {
                                    const int tap = dx * 9 + dy * 3 + dz;
                                    aa[jj][0] = fmaf(va[dz],     w[tap][jj][0], aa[jj][0]);
                                    aa[jj][1] = fmaf(va[dz + 1], w[tap][jj][1], aa[jj][1]);
                                    ab[jj][0] = fmaf(vb[dz],     w[tap][jj][0], ab[jj][0]);
                                    ab[jj][1] = fmaf(vb[dz + 1], w[tap][jj][1], ab[jj][1]);
                                }
                            }
                        }
                    }
                }
            }

            // fold deferred partials; per-batch stats
            Sa += dSaS; S2a += dS2aS;
            Sb += dSbS; S2b += dS2bS;
            const float ma  = Sa * (1.0f / 1000.0f);
            const float ra  = rsqrtf(S2a * (1.0f / 1000.0f) - ma * ma + EPSV);
            const float mb  = Sb * (1.0f / 1000.0f);
            const float rb2 = rsqrtf(S2b * (1.0f / 1000.0f) - mb * mb + EPSV);

            // epilogue both batches; store new values before the reduction
            float dSa = 0.f, dS2a = 0.f, dSb = 0.f, dS2b = 0.f;
#pragma unroll
            for (int jj = 0; jj < 2; ++jj)
#pragma unroll
                for (int kk = 0; kk < 2; ++kk) {
                    const float za = fmaf(-ma, sumw[jj][kk], aa[jj][kk]) * ra + bbv[jj][kk];
                    const float na = fmaf(rsv[jj][kk], fast_silu(za), ca[jj][kk]);
                    wra[curoff + jj * 20 + kk] = na;
                    dSa  += na - ca[jj][kk];
                    dS2a += fmaf(na, na, -ca[jj][kk] * ca[jj][kk]);
                    ca[jj][kk] = na;

                    const float zb = fmaf(-mb, sumw[jj][kk], ab[jj][kk]) * rb2 + bbv[jj][kk];
                    const float nb = fmaf(rsv[jj][kk], fast_silu(zb), cb[jj][kk]);
                    wrb[curoff + jj * 20 + kk] = nb;
                    dSb  += nb - cb[jj][kk];
                    dS2b += fmaf(nb, nb, -cb[jj][kk] * cb[jj][kk]);
                    cb[jj][kk] = nb;
                }

            // four independent butterfly chains — pipeline through shfl
#pragma unroll
            for (int o = 16; o; o >>= 1) {
                dSa  += __shfl_xor_sync(0xffffffffu, dSa,  o);
                dS2a += __shfl_xor_sync(0xffffffffu, dS2a, o);
                dSb  += __shfl_xor_sync(0xffffffffu, dSb,  o);
                dS2b += __shfl_xor_sync(0xffffffffu, dS2b, o);
            }
            const int rbp = it & 1;
            if (lane == 0) {
                red[rbp][wid * 2]     = dSa; red[rbp][wid * 2 + 1]     = dS2a;
                red[rbp][8 + wid * 2] = dSb; red[rbp][8 + wid * 2 + 1] = dS2b;
            }
            __syncthreads();
        }

        // ---- write final outputs for both batches ----
        float* Ya = Y + (size_t)ba  * 262144;
        float* Yb = Y + (size_t)bbi * 262144;
#pragma unroll
        for (int jj = 0; jj < 2; ++jj) {
            const size_t o = ((size_t)gi * 64 + gj0 + jj) * 64 + gk0;
            float2 oa; oa.x = ca[jj][0]; oa.y = ca[jj][1];
            float2 ob; ob.x = cb[jj][0]; ob.y = cb[jj][1];
            *reinterpret_cast<float2*>(Ya + o) = oa;
            *reinterpret_cast<float2*>(Yb + o) = ob;
        }
        // it=7 barrier already ordered all SMEM reads before next pass's writes.
    }
}

extern "C" void kernel_launch(void* const* d_in, const int* in_sizes, int n_in,
                              void* d_out, int out_size)
{
    const float* W  = (const float*)d_in[0];   // (27,64,64,64)
    const float* Bb = (const float*)d_in[1];   // (64,64,64)
    const float* Rs = (const float*)d_in[2];   // (64,64,64)
    const float* X  = (const float*)d_in[3];   // (16,64,64,64)
    float* Y = (float*)d_out;

    gridnet_kernel<<<2048, TPB>>>(W, Bb, Rs, X, Y);
}